// round 1
// baseline (speedup 1.0000x reference)
#include <cuda_runtime.h>

// Problem constants
#define DD 32            // D
#define MM 64            // 2*D modes
#define BB 16            // batch
#define NN 1024          // D*D
#define FF 2080          // M*(M+1)/2 output Fock states
#define FT 33            // ceil(FF/64) tiles
#define NPAIR 561        // FT*(FT+1)/2

// GEMM tiling
#define BM 64
#define BN 64
#define BK 16
#define PAD 4

// Scratch (device globals; no cudaMalloc allowed)
__device__ float g_Are[FF * NN];          // 8.5 MB
__device__ float g_Aim[FF * NN];
__device__ float g_Hre[BB * NN * NN];     // 67 MB
__device__ float g_Him[BB * NN * NN];
__device__ float g_Tre[BB * FF * NN];     // 136 MB
__device__ float g_Tim[BB * FF * NN];

// ---------------------------------------------------------------------------
// Kernel 1: amplitudes A[f, i] for f=(j,k) pair (triu order), i = x*D + y
//   A = U[j,x]*U[k,D+y] + U[k,x]*U[j,D+y], * 1/sqrt(2) when j==k
// ---------------------------------------------------------------------------
__global__ void amp_kernel(const float* __restrict__ U_re,
                           const float* __restrict__ U_im) {
    __shared__ float sUre[MM * MM];
    __shared__ float sUim[MM * MM];
    for (int t = threadIdx.x; t < MM * MM; t += blockDim.x) {
        sUre[t] = U_re[t];
        sUim[t] = U_im[t];
    }
    __syncthreads();

    int f = blockIdx.x;
    // decode (j, k) from triu row-major index
    int j = 0, rem = f;
    while (rem >= (MM - j)) { rem -= (MM - j); j++; }
    int k = j + rem;
    float scale = (j == k) ? 0.70710678118654752f : 1.0f;

    for (int i = threadIdx.x; i < NN; i += blockDim.x) {
        int x = i >> 5;
        int y = i & 31;
        float are = sUre[j * MM + x],      aim = sUim[j * MM + x];
        float bre = sUre[k * MM + DD + y], bim = sUim[k * MM + DD + y];
        float cre = sUre[k * MM + x],      cim = sUim[k * MM + x];
        float dre = sUre[j * MM + DD + y], dim_ = sUim[j * MM + DD + y];
        float re = are * bre - aim * bim + cre * dre - cim * dim_;
        float im = are * bim + aim * bre + cre * dim_ + cim * dre;
        g_Are[f * NN + i] = re * scale;
        g_Aim[f * NN + i] = im * scale;
    }
}

// ---------------------------------------------------------------------------
// Kernel 2: H = triu(rho, halved diag) + its conj-transpose  (Hermitian)
//   H[i,j] = rho[i,j] (i<j) ; conj(rho[j,i]) (i>j) ; Re(rho[i,i]) (i==j)
// ---------------------------------------------------------------------------
__global__ void herm_kernel(const float* __restrict__ rho_re,
                            const float* __restrict__ rho_im) {
    int t = blockIdx.x * blockDim.x + threadIdx.x;
    if (t >= BB * NN * NN) return;
    int b = t >> 20;
    int r = t & (NN * NN - 1);
    int i = r >> 10;
    int j = r & (NN - 1);
    float re, im;
    if (i < j) {
        re = rho_re[t]; im = rho_im[t];
    } else if (i > j) {
        int s = (b << 20) + (j << 10) + i;
        re = rho_re[s]; im = -rho_im[s];
    } else {
        re = rho_re[t]; im = 0.0f;
    }
    g_Hre[t] = re;
    g_Him[t] = im;
}

// ---------------------------------------------------------------------------
// Kernel 3: GEMM1  T[b] = A @ H[b]   ([FF x NN] = [FF x NN][NN x NN], complex)
// ---------------------------------------------------------------------------
__global__ __launch_bounds__(256) void gemm1_kernel() {
    __shared__ float As_re[BK][BM + PAD];
    __shared__ float As_im[BK][BM + PAD];
    __shared__ float Bs_re[BK][BN];
    __shared__ float Bs_im[BK][BN];

    const int b = blockIdx.z;
    const int f0 = blockIdx.y * BM;
    const int n0 = blockIdx.x * BN;
    const float* __restrict__ Hre = g_Hre + (size_t)b * NN * NN;
    const float* __restrict__ Him = g_Him + (size_t)b * NN * NN;

    const int t  = threadIdx.x;
    const int tx = t & 15;        // -> n micro-tile
    const int ty = t >> 4;        // -> f micro-tile
    const int kl  = t & 15;       // A-tile loader
    const int ml  = t >> 4;
    const int nl  = t & 63;       // B-tile loader
    const int kl2 = t >> 6;

    float cre[4][4] = {}, cim[4][4] = {};

    for (int k0 = 0; k0 < NN; k0 += BK) {
        #pragma unroll
        for (int p = 0; p < 4; p++) {
            int fr = f0 + ml + p * 16;
            float vre = 0.f, vim = 0.f;
            if (fr < FF) {
                vre = g_Are[fr * NN + k0 + kl];
                vim = g_Aim[fr * NN + k0 + kl];
            }
            As_re[kl][ml + p * 16] = vre;
            As_im[kl][ml + p * 16] = vim;
        }
        #pragma unroll
        for (int p = 0; p < 4; p++) {
            int kr = k0 + kl2 + p * 4;
            Bs_re[kl2 + p * 4][nl] = Hre[kr * NN + n0 + nl];
            Bs_im[kl2 + p * 4][nl] = Him[kr * NN + n0 + nl];
        }
        __syncthreads();

        #pragma unroll
        for (int kk = 0; kk < BK; kk++) {
            float are[4], aim[4], bre[4], bim[4];
            #pragma unroll
            for (int ii = 0; ii < 4; ii++) {
                are[ii] = As_re[kk][ty * 4 + ii];
                aim[ii] = As_im[kk][ty * 4 + ii];
            }
            #pragma unroll
            for (int jj = 0; jj < 4; jj++) {
                bre[jj] = Bs_re[kk][tx * 4 + jj];
                bim[jj] = Bs_im[kk][tx * 4 + jj];
            }
            #pragma unroll
            for (int ii = 0; ii < 4; ii++)
                #pragma unroll
                for (int jj = 0; jj < 4; jj++) {
                    cre[ii][jj] += are[ii] * bre[jj] - aim[ii] * bim[jj];
                    cim[ii][jj] += are[ii] * bim[jj] + aim[ii] * bre[jj];
                }
        }
        __syncthreads();
    }

    #pragma unroll
    for (int ii = 0; ii < 4; ii++) {
        int fr = f0 + ty * 4 + ii;
        if (fr < FF) {
            #pragma unroll
            for (int jj = 0; jj < 4; jj++) {
                g_Tre[((size_t)b * FF + fr) * NN + n0 + tx * 4 + jj] = cre[ii][jj];
                g_Tim[((size_t)b * FF + fr) * NN + n0 + tx * 4 + jj] = cim[ii][jj];
            }
        }
    }
}

// ---------------------------------------------------------------------------
// Kernel 4: GEMM2  Out[b] = T[b] @ conj(A)^T  (Hermitian output: compute
// upper tile-triangle, mirror-write conj transpose).  Out interleaved (re,im).
// ---------------------------------------------------------------------------
__global__ __launch_bounds__(256) void gemm2_kernel(float2* __restrict__ out) {
    // decode tile pair (tf, tg), tg >= tf
    int p = blockIdx.x;
    int tf = 0;
    while (p >= FT - tf) { p -= (FT - tf); tf++; }
    const int tg = tf + p;
    const int b = blockIdx.y;
    const int f0 = tf * BM;
    const int g0 = tg * BN;

    __shared__ float As_re[BK][BM + PAD];
    __shared__ float As_im[BK][BM + PAD];
    __shared__ float Bs_re[BK][BN + PAD];
    __shared__ float Bs_im[BK][BN + PAD];

    const float* __restrict__ Tre = g_Tre + (size_t)b * FF * NN;
    const float* __restrict__ Tim = g_Tim + (size_t)b * FF * NN;

    const int t  = threadIdx.x;
    const int tx = t & 15;
    const int ty = t >> 4;
    const int kl = t & 15;
    const int ml = t >> 4;

    float cre[4][4] = {}, cim[4][4] = {};

    for (int k0 = 0; k0 < NN; k0 += BK) {
        #pragma unroll
        for (int p2 = 0; p2 < 4; p2++) {
            int fr = f0 + ml + p2 * 16;
            float vre = 0.f, vim = 0.f;
            if (fr < FF) {
                vre = Tre[fr * NN + k0 + kl];
                vim = Tim[fr * NN + k0 + kl];
            }
            As_re[kl][ml + p2 * 16] = vre;
            As_im[kl][ml + p2 * 16] = vim;
        }
        #pragma unroll
        for (int p2 = 0; p2 < 4; p2++) {
            int gr = g0 + ml + p2 * 16;
            float vre = 0.f, vim = 0.f;
            if (gr < FF) {
                vre = g_Are[gr * NN + k0 + kl];
                vim = -g_Aim[gr * NN + k0 + kl];   // conj folded into load
            }
            Bs_re[kl][ml + p2 * 16] = vre;
            Bs_im[kl][ml + p2 * 16] = vim;
        }
        __syncthreads();

        #pragma unroll
        for (int kk = 0; kk < BK; kk++) {
            float are[4], aim[4], bre[4], bim[4];
            #pragma unroll
            for (int ii = 0; ii < 4; ii++) {
                are[ii] = As_re[kk][ty * 4 + ii];
                aim[ii] = As_im[kk][ty * 4 + ii];
            }
            #pragma unroll
            for (int jj = 0; jj < 4; jj++) {
                bre[jj] = Bs_re[kk][tx * 4 + jj];
                bim[jj] = Bs_im[kk][tx * 4 + jj];
            }
            #pragma unroll
            for (int ii = 0; ii < 4; ii++)
                #pragma unroll
                for (int jj = 0; jj < 4; jj++) {
                    cre[ii][jj] += are[ii] * bre[jj] - aim[ii] * bim[jj];
                    cim[ii][jj] += are[ii] * bim[jj] + aim[ii] * bre[jj];
                }
        }
        __syncthreads();
    }

    const size_t obase = (size_t)b * FF;
    #pragma unroll
    for (int ii = 0; ii < 4; ii++) {
        int fr = f0 + ty * 4 + ii;
        if (fr >= FF) continue;
        #pragma unroll
        for (int jj = 0; jj < 4; jj++) {
            int gc = g0 + tx * 4 + jj;
            if (gc >= FF) continue;
            float2 v = make_float2(cre[ii][jj], cim[ii][jj]);
            out[(obase + fr) * FF + gc] = v;
            if (tg > tf) {
                out[(obase + gc) * FF + fr] = make_float2(v.x, -v.y);
            }
        }
    }
}

// ---------------------------------------------------------------------------
extern "C" void kernel_launch(void* const* d_in, const int* in_sizes, int n_in,
                              void* d_out, int out_size) {
    const float* rho_re = (const float*)d_in[0];
    const float* rho_im = (const float*)d_in[1];
    const float* U_re   = (const float*)d_in[2];
    const float* U_im   = (const float*)d_in[3];
    float2* out = (float2*)d_out;

    amp_kernel<<<FF, 256>>>(U_re, U_im);

    int totalH = BB * NN * NN;
    herm_kernel<<<(totalH + 255) / 256, 256>>>(rho_re, rho_im);

    dim3 g1(NN / BN, FT, BB);
    gemm1_kernel<<<g1, 256>>>();

    dim3 g2(NPAIR, BB);
    gemm2_kernel<<<g2, 256>>>(out);
}

// round 3
// speedup vs baseline: 3.6550x; 3.6550x over previous
#include <cuda_runtime.h>
#include <cuda_bf16.h>
#include <cstdint>

// ---------------- problem constants ----------------
#define DD 32
#define MMODES 64
#define BB 16
#define NN 1024
#define FF 2080
#define FP 2176            // FF padded to 17*128
#define NROWT 17           // f row tiles (BM=128)
#define NCOLT 33           // g col tiles (BN=64)
#define NPAIR2 289         // sum_{tf=0..16} (33-2*tf)

// ---------------- GEMM tiling ----------------
#define BM 128
#define BN 64
#define BKC 64             // K per chunk (bf16 -> 128B rows)
#define NCH 16             // NN / BKC
#define KS 4               // k16 steps per chunk

// smem layout
#define APL 16384          // X plane: 128 rows * 128B
#define BPL 8192           // Y plane: 64 rows * 128B
#define BOFF 65536         // Y planes after 4 X planes
#define STAGE_BYTES 98304  // 4*APL + 4*BPL
#define SMEM_DYN (2 * STAGE_BYTES + 1024)

// epilogue staging (reuses stage smem)
#define PITCH_T 136
#define PLANE_T 17408      // 128 * 136
#define PITCH_O 528        // 16B-aligned float2 row pitch

// ---------------- device scratch (bf16 split planes) ----------------
__device__ __nv_bfloat16 gArh[(size_t)FP * NN];
__device__ __nv_bfloat16 gArl[(size_t)FP * NN];
__device__ __nv_bfloat16 gAih[(size_t)FP * NN];
__device__ __nv_bfloat16 gAil[(size_t)FP * NN];

__device__ __nv_bfloat16 gHrh[(size_t)BB * NN * NN];
__device__ __nv_bfloat16 gHrl[(size_t)BB * NN * NN];
__device__ __nv_bfloat16 gHih[(size_t)BB * NN * NN];
__device__ __nv_bfloat16 gHil[(size_t)BB * NN * NN];

__device__ __nv_bfloat16 gTrh[(size_t)BB * FP * NN];
__device__ __nv_bfloat16 gTrl[(size_t)BB * FP * NN];
__device__ __nv_bfloat16 gTih[(size_t)BB * FP * NN];
__device__ __nv_bfloat16 gTil[(size_t)BB * FP * NN];

// ---------------- helpers ----------------
__device__ __forceinline__ uint32_t smem_u32(const void* p) {
    uint32_t a;
    asm("{ .reg .u64 t; cvta.to.shared.u64 t, %1; cvt.u32.u64 %0, t; }" : "=r"(a) : "l"(p));
    return a;
}
#define SWZ128(off) ((off) ^ (((off) >> 3) & 0x70))

#define CPA16(dst, src) \
    asm volatile("cp.async.cg.shared.global [%0], [%1], 16;" :: "r"(dst), "l"(src))
#define CPA_COMMIT() asm volatile("cp.async.commit_group;" ::: "memory")
#define CPA_WAIT(n)  asm volatile("cp.async.wait_group %0;" :: "n"(n) : "memory")

__device__ __forceinline__ void ldsm4(uint32_t* r, uint32_t addr) {
    asm volatile("ldmatrix.sync.aligned.m8n8.x4.shared.b16 {%0,%1,%2,%3}, [%4];"
        : "=r"(r[0]), "=r"(r[1]), "=r"(r[2]), "=r"(r[3]) : "r"(addr));
}
__device__ __forceinline__ void mma16816(float* c, const uint32_t* a,
                                         uint32_t b0, uint32_t b1) {
    asm volatile(
        "mma.sync.aligned.m16n8k16.row.col.f32.bf16.bf16.f32 "
        "{%0,%1,%2,%3}, {%4,%5,%6,%7}, {%8,%9}, {%0,%1,%2,%3};"
        : "+f"(c[0]), "+f"(c[1]), "+f"(c[2]), "+f"(c[3])
        : "r"(a[0]), "r"(a[1]), "r"(a[2]), "r"(a[3]), "r"(b0), "r"(b1));
}
__device__ __forceinline__ void split2(float v, __nv_bfloat16& h, __nv_bfloat16& l) {
    h = __float2bfloat16_rn(v);
    l = __float2bfloat16_rn(v - __bfloat162float(h));
}

// ---------------------------------------------------------------------------
// Kernel 1: amplitudes -> bf16 split planes (rows >= FF zero-padded)
// ---------------------------------------------------------------------------
__global__ void amp_kernel(const float* __restrict__ U_re,
                           const float* __restrict__ U_im) {
    __shared__ float sUre[MMODES * MMODES];
    __shared__ float sUim[MMODES * MMODES];
    for (int t = threadIdx.x; t < MMODES * MMODES; t += blockDim.x) {
        sUre[t] = U_re[t];
        sUim[t] = U_im[t];
    }
    __syncthreads();

    int f = blockIdx.x;
    if (f >= FF) {
        for (int i = threadIdx.x; i < NN; i += blockDim.x) {
            size_t o = (size_t)f * NN + i;
            gArh[o] = __float2bfloat16(0.f); gArl[o] = __float2bfloat16(0.f);
            gAih[o] = __float2bfloat16(0.f); gAil[o] = __float2bfloat16(0.f);
        }
        return;
    }
    int j = 0, rem = f;
    while (rem >= (MMODES - j)) { rem -= (MMODES - j); j++; }
    int k = j + rem;
    float scale = (j == k) ? 0.70710678118654752f : 1.0f;

    for (int i = threadIdx.x; i < NN; i += blockDim.x) {
        int x = i >> 5, y = i & 31;
        float are = sUre[j * MMODES + x],       aim = sUim[j * MMODES + x];
        float bre = sUre[k * MMODES + DD + y],  bim = sUim[k * MMODES + DD + y];
        float cre = sUre[k * MMODES + x],       cim = sUim[k * MMODES + x];
        float dre = sUre[j * MMODES + DD + y],  dim_ = sUim[j * MMODES + DD + y];
        float re = (are * bre - aim * bim + cre * dre - cim * dim_) * scale;
        float im = (are * bim + aim * bre + cre * dim_ + cim * dre) * scale;
        size_t o = (size_t)f * NN + i;
        __nv_bfloat16 h, l;
        split2(re, h, l); gArh[o] = h; gArl[o] = l;
        split2(im, h, l); gAih[o] = h; gAil[o] = l;
    }
}

// ---------------------------------------------------------------------------
// Kernel 2: Hermitian H build (tiled) -> bf16 split planes
// ---------------------------------------------------------------------------
#define HT 32
__global__ __launch_bounds__(256) void herm_kernel(const float* __restrict__ rho_re,
                                                   const float* __restrict__ rho_im) {
    int p = blockIdx.x, ti = 0;
    while (p >= (HT - ti)) { p -= (HT - ti); ti++; }
    int tj = ti + p;
    int b = blockIdx.y;

    __shared__ float sRe[HT][HT + 1];
    __shared__ float sIm[HT][HT + 1];

    size_t base = (size_t)b * NN * NN;
    int r0 = ti * HT, c0 = tj * HT;
    int t = threadIdx.x;

    #pragma unroll
    for (int it = 0; it < 4; it++) {
        int slot = it * 256 + t;
        int r = slot >> 5, c = slot & 31;
        size_t g = base + (size_t)(r0 + r) * NN + c0 + c;
        sRe[r][c] = rho_re[g];
        sIm[r][c] = rho_im[g];
    }
    __syncthreads();

    #pragma unroll
    for (int it = 0; it < 4; it++) {
        int slot = it * 256 + t;
        int r = slot >> 5, c = slot & 31;
        float vre, vim;
        if (ti < tj) { vre = sRe[r][c]; vim = sIm[r][c]; }
        else if (r < c) { vre = sRe[r][c]; vim = sIm[r][c]; }
        else if (r > c) { vre = sRe[c][r]; vim = -sIm[c][r]; }
        else { vre = sRe[r][c]; vim = 0.0f; }
        size_t o = base + (size_t)(r0 + r) * NN + c0 + c;
        __nv_bfloat16 h, l;
        split2(vre, h, l); gHrh[o] = h; gHrl[o] = l;
        split2(vim, h, l); gHih[o] = h; gHil[o] = l;
    }
    if (ti < tj) {
        #pragma unroll
        for (int it = 0; it < 4; it++) {
            int slot = it * 256 + t;
            int r = slot >> 5, c = slot & 31;
            float vre = sRe[c][r], vim = -sIm[c][r];
            size_t o = base + (size_t)(c0 + r) * NN + r0 + c;
            __nv_bfloat16 h, l;
            split2(vre, h, l); gHrh[o] = h; gHrl[o] = l;
            split2(vim, h, l); gHih[o] = h; gHil[o] = l;
        }
    }
}

// ---------------------------------------------------------------------------
// Unified split-bf16 complex GEMM via mma.sync:  C = X * conj(Y)^T
//   mode 0: X = Amp[f0..], Y = H rows [b, n0..]   -> bf16-split T
//   mode 1: X = T[b, f0..], Y = Amp[g0..]         -> float2 out (+ conj mirror)
// planes: 0=re_hi 1=re_lo 2=im_hi 3=im_lo
// re = XrYr + XiYi ; im = XiYr - XrYi  (Yi fragments sign-flipped for the -)
// ---------------------------------------------------------------------------
__global__ __launch_bounds__(256, 1) void gemm_kernel(int mode, float2* __restrict__ out) {
    extern __shared__ char dsm[];
    uint32_t sbraw = smem_u32(dsm);
    uint32_t sb = (sbraw + 1023u) & ~1023u;
    char* smem = dsm + (sb - sbraw);

    const int t = threadIdx.x;
    const int lane = t & 31;
    const int wid = t >> 5;
    const int wm = wid & 3;       // 4 warps along M (32 rows each)
    const int wn = wid >> 2;      // 2 warps along N (32 cols each)

    int b, f0, n0, tf = 0, tg = 0;
    const __nv_bfloat16 *Ap[4], *Bp[4];
    if (mode == 0) {
        b = blockIdx.z; f0 = blockIdx.y * BM; n0 = blockIdx.x * BN;
        size_t ab = (size_t)f0 * NN;
        Ap[0] = gArh + ab; Ap[1] = gArl + ab; Ap[2] = gAih + ab; Ap[3] = gAil + ab;
        size_t bbo = ((size_t)b * NN + n0) * NN;
        Bp[0] = gHrh + bbo; Bp[1] = gHrl + bbo; Bp[2] = gHih + bbo; Bp[3] = gHil + bbo;
    } else {
        b = blockIdx.y;
        int p = blockIdx.x;
        while (p >= (NCOLT - 2 * tf)) { p -= (NCOLT - 2 * tf); tf++; }
        tg = 2 * tf + p;
        f0 = tf * BM; n0 = tg * BN;
        size_t ab = ((size_t)b * FP + f0) * NN;
        Ap[0] = gTrh + ab; Ap[1] = gTrl + ab; Ap[2] = gTih + ab; Ap[3] = gTil + ab;
        size_t bbo = (size_t)n0 * NN;
        Bp[0] = gArh + bbo; Bp[1] = gArl + bbo; Bp[2] = gAih + bbo; Bp[3] = gAil + bbo;
    }

    // ---- prefetch helper (24 cp.async per thread per stage) ----
    auto prefetch = [&](int stOff, int k0) {
        #pragma unroll
        for (int it = 0; it < 16; it++) {            // X: 4096 16B chunks
            int slot = it * 256 + t;
            int v = slot >> 10;
            int rem = slot & 1023;
            int row = rem >> 3, c16 = rem & 7;
            uint32_t dst = sb + stOff + v * APL + SWZ128(row * 128 + c16 * 16);
            const char* src = (const char*)(Ap[v] + (size_t)row * NN + k0) + c16 * 16;
            CPA16(dst, src);
        }
        #pragma unroll
        for (int it = 0; it < 8; it++) {             // Y: 2048 16B chunks
            int slot = it * 256 + t;
            int v = slot >> 9;
            int rem = slot & 511;
            int row = rem >> 3, c16 = rem & 7;
            uint32_t dst = sb + stOff + BOFF + v * BPL + SWZ128(row * 128 + c16 * 16);
            const char* src = (const char*)(Bp[v] + (size_t)row * NN + k0) + c16 * 16;
            CPA16(dst, src);
        }
    };

    float accR[2][4][4];
    float accI[2][4][4];
    #pragma unroll
    for (int mt = 0; mt < 2; mt++)
        #pragma unroll
        for (int nt = 0; nt < 4; nt++)
            #pragma unroll
            for (int q = 0; q < 4; q++) { accR[mt][nt][q] = 0.f; accI[mt][nt][q] = 0.f; }

    // per-lane ldmatrix row/addr constants
    const int lrow = lane & 15;
    const int lhalf = (lane >> 4) * 16;
    // A: rows wm*32 + mt*16 + lrow ; B: rows wn*32 + pair*16 + lrow
    uint32_t aRowBase[2], bRowBase[2], aXm[2], bXm[2];
    #pragma unroll
    for (int mt = 0; mt < 2; mt++) {
        int row = wm * 32 + mt * 16 + lrow;
        aRowBase[mt] = row * 128;
        aXm[mt] = (row & 7) * 16;
    }
    #pragma unroll
    for (int pr = 0; pr < 2; pr++) {
        int row = wn * 32 + pr * 16 + lrow;
        bRowBase[pr] = row * 128;
        bXm[pr] = (row & 7) * 16;
    }

    prefetch(0, 0);
    CPA_COMMIT();

    for (int c = 0; c < NCH; c++) {
        if (c + 1 < NCH) {
            prefetch(((c + 1) & 1) * STAGE_BYTES, (c + 1) * BKC);
            CPA_COMMIT();
            CPA_WAIT(1);
        } else {
            CPA_WAIT(0);
        }
        __syncthreads();

        const uint32_t stBase = sb + (c & 1) * STAGE_BYTES;

        #pragma unroll
        for (int ks = 0; ks < KS; ks++) {
            const uint32_t xoff = ks * 32 + lhalf;
            uint32_t Af[2][4][4];
            #pragma unroll
            for (int mt = 0; mt < 2; mt++)
                #pragma unroll
                for (int v = 0; v < 4; v++)
                    ldsm4(Af[mt][v], stBase + v * APL + aRowBase[mt] + (xoff ^ aXm[mt]));

            uint32_t Bf[4][2][4];
            #pragma unroll
            for (int v = 0; v < 4; v++)
                #pragma unroll
                for (int pr = 0; pr < 2; pr++)
                    ldsm4(Bf[v][pr], stBase + BOFF + v * BPL + bRowBase[pr] + (xoff ^ bXm[pr]));

            // negated Yi fragments (planes 2,3) for the im accumulation
            uint32_t nB2[2][4], nB3[2][4];
            #pragma unroll
            for (int pr = 0; pr < 2; pr++)
                #pragma unroll
                for (int q = 0; q < 4; q++) {
                    nB2[pr][q] = Bf[2][pr][q] ^ 0x80008000u;
                    nB3[pr][q] = Bf[3][pr][q] ^ 0x80008000u;
                }

            #pragma unroll
            for (int mt = 0; mt < 2; mt++) {
                #pragma unroll
                for (int nt = 0; nt < 4; nt++) {
                    const int pr = nt >> 1, hh = nt & 1;
                    uint32_t brh0 = Bf[0][pr][hh], brh1 = Bf[0][pr][hh + 2];
                    uint32_t brl0 = Bf[1][pr][hh], brl1 = Bf[1][pr][hh + 2];
                    uint32_t bih0 = Bf[2][pr][hh], bih1 = Bf[2][pr][hh + 2];
                    uint32_t bil0 = Bf[3][pr][hh], bil1 = Bf[3][pr][hh + 2];
                    uint32_t nih0 = nB2[pr][hh],  nih1 = nB2[pr][hh + 2];
                    uint32_t nil0 = nB3[pr][hh],  nil1 = nB3[pr][hh + 2];
                    float* cr = accR[mt][nt];
                    float* ci = accI[mt][nt];
                    // re: XrYr (3 split terms) + XiYi (3)
                    mma16816(cr, Af[mt][0], brh0, brh1);
                    mma16816(cr, Af[mt][0], brl0, brl1);
                    mma16816(cr, Af[mt][1], brh0, brh1);
                    mma16816(cr, Af[mt][2], bih0, bih1);
                    mma16816(cr, Af[mt][2], bil0, bil1);
                    mma16816(cr, Af[mt][3], bih0, bih1);
                    // im: XiYr (3) + Xr*(-Yi) (3)
                    mma16816(ci, Af[mt][2], brh0, brh1);
                    mma16816(ci, Af[mt][2], brl0, brl1);
                    mma16816(ci, Af[mt][3], brh0, brh1);
                    mma16816(ci, Af[mt][0], nih0, nih1);
                    mma16816(ci, Af[mt][0], nil0, nil1);
                    mma16816(ci, Af[mt][1], nih0, nih1);
                }
            }
        }
        __syncthreads();
    }

    // ---- epilogue: fragments -> smem staging (reuse stage memory) ----
    const int erow0 = wm * 32 + (lane >> 2);
    const int ecol0 = wn * 32 + (lane & 3) * 2;

    if (mode == 0) {
        #pragma unroll
        for (int mt = 0; mt < 2; mt++)
            #pragma unroll
            for (int nt = 0; nt < 4; nt++) {
                int col = ecol0 + nt * 8;
                #pragma unroll
                for (int hlf = 0; hlf < 2; hlf++) {
                    int row = erow0 + mt * 16 + hlf * 8;
                    float re0 = accR[mt][nt][hlf * 2 + 0], re1 = accR[mt][nt][hlf * 2 + 1];
                    float im0 = accI[mt][nt][hlf * 2 + 0], im1 = accI[mt][nt][hlf * 2 + 1];
                    __nv_bfloat16 h0, l0, h1, l1;
                    split2(re0, h0, l0); split2(re1, h1, l1);
                    *(__nv_bfloat162*)(smem + 0 * PLANE_T + row * PITCH_T + col * 2) =
                        __nv_bfloat162(h0, h1);
                    *(__nv_bfloat162*)(smem + 1 * PLANE_T + row * PITCH_T + col * 2) =
                        __nv_bfloat162(l0, l1);
                    split2(im0, h0, l0); split2(im1, h1, l1);
                    *(__nv_bfloat162*)(smem + 2 * PLANE_T + row * PITCH_T + col * 2) =
                        __nv_bfloat162(h0, h1);
                    *(__nv_bfloat162*)(smem + 3 * PLANE_T + row * PITCH_T + col * 2) =
                        __nv_bfloat162(l0, l1);
                }
            }
        __syncthreads();

        __nv_bfloat16* Td[4];
        size_t tb0 = ((size_t)b * FP + f0) * NN + n0;
        Td[0] = gTrh + tb0; Td[1] = gTrl + tb0; Td[2] = gTih + tb0; Td[3] = gTil + tb0;
        #pragma unroll
        for (int v = 0; v < 4; v++) {
            #pragma unroll
            for (int it = 0; it < 8; it++) {
                int slot = it * 256 + t;
                int row = slot >> 4, c8 = slot & 15;
                uint2 val = *(uint2*)(smem + v * PLANE_T + row * PITCH_T + c8 * 8);
                *(uint2*)(Td[v] + (size_t)row * NN + c8 * 4) = val;
            }
        }
    } else {
        #pragma unroll
        for (int mt = 0; mt < 2; mt++)
            #pragma unroll
            for (int nt = 0; nt < 4; nt++) {
                int col = ecol0 + nt * 8;
                #pragma unroll
                for (int hlf = 0; hlf < 2; hlf++) {
                    int row = erow0 + mt * 16 + hlf * 8;
                    float4 v4;
                    v4.x = accR[mt][nt][hlf * 2 + 0];
                    v4.y = accI[mt][nt][hlf * 2 + 0];
                    v4.z = accR[mt][nt][hlf * 2 + 1];
                    v4.w = accI[mt][nt][hlf * 2 + 1];
                    *(float4*)(smem + row * PITCH_O + col * 8) = v4;
                }
            }
        __syncthreads();

        const size_t obase = (size_t)b * FF;
        #pragma unroll 4
        for (int it = 0; it < 32; it++) {
            int slot = it * 256 + t;
            int row = slot >> 6, cc = slot & 63;
            int fr = f0 + row, gc = n0 + cc;
            if (fr < FF && gc < FF) {
                float2 v = *(float2*)(smem + row * PITCH_O + cc * 8);
                out[(obase + fr) * FF + gc] = v;
            }
        }
        if (tg >= 2 * tf + 2) {   // off-band: mirror conj-transpose
            #pragma unroll 4
            for (int it = 0; it < 32; it++) {
                int slot = it * 256 + t;
                int g = slot >> 7, ff = slot & 127;
                int gr = n0 + g, fc = f0 + ff;
                if (gr < FF && fc < FF) {
                    float2 v = *(float2*)(smem + ff * PITCH_O + g * 8);
                    out[(obase + gr) * FF + fc] = make_float2(v.x, -v.y);
                }
            }
        }
    }
}

// ---------------------------------------------------------------------------
extern "C" void kernel_launch(void* const* d_in, const int* in_sizes, int n_in,
                              void* d_out, int out_size) {
    const float* rho_re = (const float*)d_in[0];
    const float* rho_im = (const float*)d_in[1];
    const float* U_re   = (const float*)d_in[2];
    const float* U_im   = (const float*)d_in[3];
    float2* out = (float2*)d_out;

    static int attr_set = 0;
    if (!attr_set) {
        cudaFuncSetAttribute(gemm_kernel, cudaFuncAttributeMaxDynamicSharedMemorySize, SMEM_DYN);
        attr_set = 1;
    }

    amp_kernel<<<FP, 256>>>(U_re, U_im);

    dim3 hg(HT * (HT + 1) / 2, BB);
    herm_kernel<<<hg, 256>>>(rho_re, rho_im);

    dim3 g1(NN / BN, NROWT, BB);
    gemm_kernel<<<g1, 256, SMEM_DYN>>>(0, nullptr);

    dim3 g2(NPAIR2, BB);
    gemm_kernel<<<g2, 256, SMEM_DYN>>>(1, out);
}